// round 12
// baseline (speedup 1.0000x reference)
#include <cuda_runtime.h>
#include <cstdint>

#define N_TOK 8192
#define HID   8192
#define NG    16
#define NE    16

#define BM     64
#define NTHR   512
#define NSUP   128                // stages of 64 k
#define NSLOT  8
#define DEPTH  7                  // outstanding slots
#define XROW_B 288                // padded X row stride (72 words ≡ 8 mod 32)
#define W_OFF  (64 * XROW_B)      // 18432
#define WBLK_B 6144               // W bytes per 64-k block
#define SLOT_B (W_OFF + WBLK_B)   // 24576
#define SMEM_DYN (NSLOT * SLOT_B) // 196608
#define TXB    (64 * 256 + WBLK_B)   // 22528
#define WSTG_W 1536               // W words per 64-k block (hi 768 + lo 768, rows padded 24)

typedef unsigned long long ull;

// ---------------- device scratch ----------------
__device__ uint32_t d_w1s[128 * WSTG_W];
__device__ uint32_t d_wms[NG * 128 * WSTG_W];      // 12.6MB
__device__ float d_gsum[NG];
__device__ float d_msum[NE];
__device__ int   d_gsel[N_TOK];
__device__ int   d_gcount[NG];
__device__ int   d_gcur[NG];
__device__ int   d_perm[N_TOK];
__device__ int   d_done;

// ---------------- helpers ----------------
__device__ __forceinline__ uint32_t s2u(const void* p) {
    return (uint32_t)__cvta_generic_to_shared(p);
}
__device__ __forceinline__ void bulkcp(uint32_t dst, const void* src, uint32_t n, uint32_t mbar) {
    asm volatile(
        "cp.async.bulk.shared::cluster.global.mbarrier::complete_tx::bytes [%0], [%1], %2, [%3];"
        :: "r"(dst), "l"(src), "r"(n), "r"(mbar) : "memory");
}
#define MB_INIT(a, c) asm volatile("mbarrier.init.shared.b64 [%0], %1;" :: "r"(a), "r"(c) : "memory")
#define MB_EXPECT(a, tx) asm volatile("mbarrier.arrive.expect_tx.shared.b64 _, [%0], %1;" :: "r"(a), "r"(tx) : "memory")
__device__ __forceinline__ void mb_wait(uint32_t mb, uint32_t parity) {
    asm volatile(
        "{\n\t.reg .pred P;\n\t"
        "WL_%=:\n\t"
        "mbarrier.try_wait.parity.acquire.cta.shared::cta.b64 P, [%0], %1, 0x989680;\n\t"
        "@P bra.uni WD_%=;\n\t"
        "bra.uni WL_%=;\n\t"
        "WD_%=:\n\t}"
        :: "r"(mb), "r"(parity) : "memory");
}
__device__ __forceinline__ uint32_t pkbf(float v0, float v1) {
    uint32_t d;
    asm("cvt.rn.bf16x2.f32 %0, %1, %2;" : "=r"(d) : "f"(v1), "f"(v0));
    return d;
}
__device__ __forceinline__ void split2(float v0, float v1, uint32_t& hi, uint32_t& lo) {
    hi = pkbf(v0, v1);
    float h0 = __uint_as_float(hi << 16);
    float h1 = __uint_as_float(hi & 0xFFFF0000u);
    lo = pkbf(v0 - h0, v1 - h1);
}
__device__ __forceinline__ void mma16(float* d, const uint32_t* a, uint32_t b0, uint32_t b1) {
    asm volatile(
        "mma.sync.aligned.m16n8k16.row.col.f32.bf16.bf16.f32 "
        "{%0,%1,%2,%3}, {%4,%5,%6,%7}, {%8,%9}, {%0,%1,%2,%3};"
        : "+f"(d[0]), "+f"(d[1]), "+f"(d[2]), "+f"(d[3])
        : "r"(a[0]), "r"(a[1]), "r"(a[2]), "r"(a[3]), "r"(b0), "r"(b1));
}

// ============================================================
// Prep W1 (tiny) + zero scalars. 256 blocks.
// ============================================================
__global__ void k_prep_w1(const float* __restrict__ W1)
{
    const int idx = blockIdx.x * 256 + threadIdx.x;   // -> 65536
    const int s = idx >> 9, kp = (idx >> 4) & 31, n = idx & 15;
    const int k = s * 64 + kp * 2;
    uint32_t hi, lo;
    split2(W1[(size_t)n * HID + k], W1[(size_t)n * HID + k + 1], hi, lo);
    d_w1s[s * WSTG_W + kp * 24 + n] = hi;
    d_w1s[s * WSTG_W + 768 + kp * 24 + n] = lo;
    if (idx < NG) {
        d_gsum[idx] = 0.f;
        d_msum[idx] = 0.f;
        d_gcount[idx] = 0;
        d_gcur[idx] = 0;
        if (idx == 0) d_done = 0;
    }
}

// ============================================================
// Scatter (blocks 0..31) + WM prep (blocks 32..4127), one launch.
// ============================================================
__global__ void k_scatter_prep(const float* __restrict__ WM)
{
    const int tid = threadIdx.x;
    if (blockIdx.x >= 32) {
        const int idx = (blockIdx.x - 32) * 256 + tid;    // -> 1048576
        const int g = idx >> 16, s = (idx >> 9) & 127, kp = (idx >> 4) & 31, n = idx & 15;
        const float* src = WM + ((size_t)(g * HID) + s * 64 + kp * 2) * NE + n;
        uint32_t hi, lo;
        split2(src[0], src[NE], hi, lo);
        uint32_t* dst = d_wms + (size_t)g * (128 * WSTG_W) + s * WSTG_W + kp * 24 + n;
        dst[0] = hi;
        dst[768] = lo;
        return;
    }
    __shared__ int cnt[NG], base[NG];
    if (tid < NG) cnt[tid] = 0;
    __syncthreads();
    const int n = blockIdx.x * 256 + tid;
    const int g = d_gsel[n];
    const int rr = atomicAdd(&cnt[g], 1);
    __syncthreads();
    if (tid < NG) {
        int goff = 0;
        for (int h = 0; h < NG; h++)
            if (h < tid) goff += d_gcount[h];
        base[tid] = goff + atomicAdd(&d_gcur[tid], cnt[tid]);
    }
    __syncthreads();
    d_perm[base[g] + rr] = n;
}

// ============================================================
// Core GEMM: C[64 tok x 16] = X . W^T, bf16 HMMA 3-term split,
// 8-slot bulk-copy ring, one 64-k block per slot, 7 outstanding.
// Warp w (0..15): mt = w&3 (m16 tile), kh = w>>2 (k16 quarter).
// myrow: per-thread X row base (used by tid<64). wbase: W split source.
// ============================================================
__device__ __forceinline__ void gemm_core(char* sm, const char* myrow,
                                          const char* wbase, int tid,
                                          float* red, ull* mbs)
{
    const int w = tid >> 5, lane = tid & 31;
    const int mt = w & 3, kh = w >> 2;
    const int q = lane >> 2, c = lane & 3;
    const uint32_t smb = s2u(sm);

    if (tid < NSLOT) MB_INIT(s2u(&mbs[tid]), 1);
    __syncthreads();
    uint32_t mba[NSLOT];
#pragma unroll
    for (int i = 0; i < NSLOT; i++) mba[i] = s2u(&mbs[i]);

#define GISSUE(s_) do {                                                  \
        const uint32_t slot_ = (s_) & (NSLOT - 1);                       \
        const uint32_t b_ = slot_ * SLOT_B;                              \
        if (tid < 64) {                                                  \
            bulkcp(smb + b_ + tid * XROW_B,                              \
                   myrow + (size_t)(s_) * 256, 256, mba[slot_]);         \
        } else if (tid == 64) {                                          \
            MB_EXPECT(mba[slot_], TXB);                                  \
            bulkcp(smb + b_ + W_OFF,                                     \
                   wbase + (size_t)(s_) * WBLK_B, WBLK_B, mba[slot_]);   \
        }                                                                \
    } while (0)

    // prologue: DEPTH slots outstanding
#pragma unroll
    for (int p = 0; p < DEPTH; p++) GISSUE(p);

    // ---- A fragment offsets ----
    uint32_t offA[4];
#pragma unroll
    for (int j = 0; j < 4; j++) {
        const int row = mt * 16 + q + (j & 1) * 8;
        const int kp = kh * 8 + c + (j >> 1) * 4;
        offA[j] = row * XROW_B + kp * 8;
    }
    // ---- B fragment offsets (hi; lo = +3072): [nt][b01] ----
    uint32_t offB[2][2];
#pragma unroll
    for (int nt = 0; nt < 2; nt++) {
        const int n = nt * 8 + q;
        offB[nt][0] = W_OFF + ((kh * 8 + c) * 24 + n) * 4;
        offB[nt][1] = W_OFF + ((kh * 8 + c + 4) * 24 + n) * 4;
    }

    float acc[2][4];
#pragma unroll
    for (int nt = 0; nt < 2; nt++)
#pragma unroll
        for (int i = 0; i < 4; i++) acc[nt][i] = 0.f;

    for (int S = 0; S < NSUP; S++) {
        const uint32_t slot = S & (NSLOT - 1);
        mb_wait(mba[slot], (S >> 3) & 1);

        const char* bb = sm + slot * SLOT_B;
        uint32_t ah[4], al[4];
#pragma unroll
        for (int j = 0; j < 4; j++) {
            float2 v = *(const float2*)(bb + offA[j]);
            split2(v.x, v.y, ah[j], al[j]);
        }
#pragma unroll
        for (int nt = 0; nt < 2; nt++) {
            const uint32_t bh0 = *(const uint32_t*)(bb + offB[nt][0]);
            const uint32_t bh1 = *(const uint32_t*)(bb + offB[nt][1]);
            const uint32_t bl0 = *(const uint32_t*)(bb + offB[nt][0] + 3072);
            const uint32_t bl1 = *(const uint32_t*)(bb + offB[nt][1] + 3072);
            mma16(acc[nt], ah, bh0, bh1);   // ah*bh
            mma16(acc[nt], ah, bl0, bl1);   // ah*bl
            mma16(acc[nt], al, bh0, bh1);   // al*bh  (al*bl dropped)
        }
        __syncthreads();        // slot fully consumed by all warps
        if (S + DEPTH < NSUP) GISSUE(S + DEPTH);
    }
#undef GISSUE

    // ---- cross-kh reduction (4 slices) into red[64][17] ----
    for (int step = 0; step < 4; step++) {
        if (kh == step) {
#pragma unroll
            for (int nt = 0; nt < 2; nt++) {
                const int r0 = mt * 16 + q, cc = nt * 8 + 2 * c;
                if (step == 0) {
                    red[r0 * 17 + cc]           = acc[nt][0];
                    red[r0 * 17 + cc + 1]       = acc[nt][1];
                    red[(r0 + 8) * 17 + cc]     = acc[nt][2];
                    red[(r0 + 8) * 17 + cc + 1] = acc[nt][3];
                } else {
                    red[r0 * 17 + cc]           += acc[nt][0];
                    red[r0 * 17 + cc + 1]       += acc[nt][1];
                    red[(r0 + 8) * 17 + cc]     += acc[nt][2];
                    red[(r0 + 8) * 17 + cc + 1] += acc[nt][3];
                }
            }
        }
        __syncthreads();
    }
}

// ============================================================
// Kernel 1: group-gate GEMM + softmax/argmax/sums/hist
// ============================================================
__global__ void __launch_bounds__(NTHR, 1)
k_gemm1(const float* __restrict__ X)
{
    extern __shared__ __align__(16) char sm[];
    __shared__ ull mbs[NSLOT];
    __shared__ int shist[NG];
    const int tid = threadIdx.x;
    if (tid < NG) shist[tid] = 0;

    const char* myrow = (const char*)(X + (size_t)(blockIdx.x * BM + (tid & 63)) * HID);
    float* red = (float*)sm;
    gemm_core(sm, myrow, (const char*)d_w1s, tid, red, mbs);

    float* pb = (float*)(sm + 4608);   // [64][17]
    if (tid < BM) {
        float lg[NG];
#pragma unroll
        for (int g = 0; g < NG; g++) lg[g] = red[tid * 17 + g];
        float mx = lg[0];
        int gi = 0;
#pragma unroll
        for (int g = 1; g < NG; g++)
            if (lg[g] > mx) { mx = lg[g]; gi = g; }
        float p[NG], ss = 0.f;
#pragma unroll
        for (int g = 0; g < NG; g++) { p[g] = __expf(lg[g] - mx); ss += p[g]; }
        const float inv = 1.0f / ss;
#pragma unroll
        for (int g = 0; g < NG; g++) pb[tid * 17 + g] = p[g] * inv;
        d_gsel[blockIdx.x * BM + tid] = gi;
        atomicAdd(&shist[gi], 1);
    }
    __syncthreads();
    if (tid < NG) {
        float s = 0.f;
        for (int t = 0; t < BM; t++) s += pb[t * 17 + tid];
        atomicAdd(&d_gsum[tid], s);
        atomicAdd(&d_gcount[tid], shist[tid]);
    }
}

// ============================================================
// Kernel 2: mini-gate GEMM (gathered rows) + top-4 + aux finalize
// ============================================================
__device__ __forceinline__ void tick_final(float* out, int out_size, int nblk)
{
    __threadfence();
    const int t = atomicAdd(&d_done, 1);
    if (t == nblk - 1) {
        __threadfence();
        float a = 0.f;
        for (int i = 0; i < NG; i++) { float x = d_gsum[i] / (float)N_TOK; a += x * x; }
        for (int i = 0; i < NE; i++) { float x = d_msum[i] / (float)N_TOK; a += x * x; }
        out[out_size - 1] = a;
    }
}

__global__ void __launch_bounds__(NTHR, 1)
k_gemm2(const float* __restrict__ X, float* __restrict__ out, int out_size)
{
    const int g = blockIdx.y;
    const int cnt = d_gcount[g];
    const int start = blockIdx.x * BM;
    const int nblk = gridDim.x * gridDim.y;
    const int tid = threadIdx.x;
    if (start >= cnt) {
        if (tid == 0) tick_final(out, out_size, nblk);
        return;
    }
    const int nvalid = min(BM, cnt - start);

    extern __shared__ __align__(16) char sm[];
    __shared__ ull mbs[NSLOT];
    __shared__ int rows_s[BM];
    if (tid == 0) {            // local prefix: offset of group g
        int off = 0;
        for (int h = 0; h < NG; h++)
            if (h < g) off += d_gcount[h];
        rows_s[0] = off;       // temp
    }
    __syncthreads();
    const int off = rows_s[0];
    __syncthreads();
    if (tid < BM) {
        int ix = start + tid;
        if (ix >= cnt) ix = cnt - 1;   // clamp: duplicate rows, discarded
        rows_s[tid] = d_perm[off + ix];
    }
    __syncthreads();

    const char* myrow = (const char*)(X + (size_t)rows_s[tid & 63] * HID);
    const char* wbase = (const char*)(d_wms + (size_t)g * (128 * WSTG_W));
    float* red = (float*)sm;
    gemm_core(sm, myrow, wbase, tid, red, mbs);

    float* pb = (float*)(sm + 4608);   // [64][17]
    if (tid < BM) {
        const bool valid = (tid < nvalid);
        float lg[NE];
#pragma unroll
        for (int e = 0; e < NE; e++) lg[e] = red[tid * 17 + e];
        float mx = lg[0];
#pragma unroll
        for (int e = 1; e < NE; e++) mx = fmaxf(mx, lg[e]);
        float ex[NE], ss = 0.f;
#pragma unroll
        for (int e = 0; e < NE; e++) { ex[e] = __expf(lg[e] - mx); ss += ex[e]; }
        const float inv = 1.0f / ss;
#pragma unroll
        for (int e = 0; e < NE; e++) pb[tid * 17 + e] = valid ? ex[e] * inv : 0.f;

        if (valid) {
            // top-4 by logit; strict > keeps lowest index on ties (lax.top_k order)
            float cur[NE];
#pragma unroll
            for (int e = 0; e < NE; e++) cur[e] = lg[e];
            int eidx[4];
            float ev[4], den = 0.f;
#pragma unroll
            for (int j = 0; j < 4; j++) {
                float best = -3.4e38f;
                int bi = 0;
#pragma unroll
                for (int e = 0; e < NE; e++)
                    if (cur[e] > best) { best = cur[e]; bi = e; }
                cur[bi] = -3.4e38f;
                eidx[j] = bi;
                ev[j] = ex[bi];
                den += ex[bi];
            }
            // group prob cancels in normalization: final = ex_j / sum(top4 ex)
            const float invd = 1.0f / den;
            const int n = rows_s[tid];
#pragma unroll
            for (int j = 0; j < 4; j++) {
                out[(size_t)n * 4 + j] = ev[j] * invd;
                out[(size_t)N_TOK * 4 + (size_t)n * 4 + j] = (float)(g * NE + eidx[j]);
            }
        }
    }
    __syncthreads();
    if (tid < NE) {
        float s = 0.f;
        for (int t = 0; t < BM; t++) s += pb[t * 17 + tid];
        atomicAdd(&d_msum[tid], s);
    }
    __syncthreads();
    if (tid == 0) tick_final(out, out_size, nblk);
}

// ============================================================
extern "C" void kernel_launch(void* const* d_in, const int* in_sizes, int n_in,
                              void* d_out, int out_size)
{
    const float* X  = (const float*)d_in[0];  // hidden_states [N, H]
    const float* W1 = (const float*)d_in[1];  // group_gate_w  [16, H]
    const float* WM = (const float*)d_in[2];  // mini_gates    [16, H, 16]
    float* out = (float*)d_out;               // [probs N*4 | indices N*4 | aux]

    cudaFuncSetAttribute(k_gemm1, cudaFuncAttributeMaxDynamicSharedMemorySize, SMEM_DYN);
    cudaFuncSetAttribute(k_gemm2, cudaFuncAttributeMaxDynamicSharedMemorySize, SMEM_DYN);

    k_prep_w1<<<256, 256>>>(W1);                                          // launch 1
    k_gemm1<<<N_TOK / BM, NTHR, SMEM_DYN>>>(X);                           // launch 2
    k_scatter_prep<<<32 + 4096, 256>>>(WM);                               // launch 3
    k_gemm2<<<dim3(N_TOK / BM, NG), NTHR, SMEM_DYN>>>(X, out, out_size);  // launch 4 (ncu slot)
}

// round 13
// speedup vs baseline: 2.2503x; 2.2503x over previous
#include <cuda_runtime.h>
#include <cstdint>

#define N_TOK 8192
#define HID   8192
#define NG    16
#define NE    16

#define BM     64
#define NTHR   512
#define NSUP   32                 // superstages of 256 k
#define XROW_B 1056               // padded X row stride (word off ≡ 8 mod 32)
#define W_OFF  (64 * XROW_B)      // 67584
#define WSUP_B 24576              // W bytes per superstage (4 x 6144)
#define SLOT_B (W_OFF + WSUP_B)   // 92160
#define SMEM_DYN (2 * SLOT_B)     // 184320
#define TXB    (64 * 1024 + WSUP_B)  // 90112
#define WSTG_W 1536               // W words per 64-k block (hi 768 + lo 768, rows padded 24)

typedef unsigned long long ull;

// ---------------- device scratch ----------------
__device__ uint32_t d_w1s[128 * WSTG_W];
__device__ uint32_t d_wms[NG * 128 * WSTG_W];      // 12.6MB
__device__ float d_gsum[NG];
__device__ float d_msum[NE];
__device__ int   d_gsel[N_TOK];
__device__ int   d_gcount[NG];
__device__ int   d_gcur[NG];
__device__ int   d_perm[N_TOK];
__device__ int   d_done;

// ---------------- helpers ----------------
__device__ __forceinline__ uint32_t s2u(const void* p) {
    return (uint32_t)__cvta_generic_to_shared(p);
}
__device__ __forceinline__ void bulkcp(uint32_t dst, const void* src, uint32_t n, uint32_t mbar) {
    asm volatile(
        "cp.async.bulk.shared::cluster.global.mbarrier::complete_tx::bytes [%0], [%1], %2, [%3];"
        :: "r"(dst), "l"(src), "r"(n), "r"(mbar) : "memory");
}
#define MB_INIT(a, c) asm volatile("mbarrier.init.shared.b64 [%0], %1;" :: "r"(a), "r"(c) : "memory")
#define MB_EXPECT(a, tx) asm volatile("mbarrier.arrive.expect_tx.shared.b64 _, [%0], %1;" :: "r"(a), "r"(tx) : "memory")
#define MB_ARRIVE(a) asm volatile("mbarrier.arrive.shared.b64 _, [%0];" :: "r"(a) : "memory")
__device__ __forceinline__ void mb_wait(uint32_t mb, uint32_t parity) {
    asm volatile(
        "{\n\t.reg .pred P;\n\t"
        "WL_%=:\n\t"
        "mbarrier.try_wait.parity.acquire.cta.shared::cta.b64 P, [%0], %1, 0x989680;\n\t"
        "@P bra.uni WD_%=;\n\t"
        "bra.uni WL_%=;\n\t"
        "WD_%=:\n\t}"
        :: "r"(mb), "r"(parity) : "memory");
}
__device__ __forceinline__ uint32_t pkbf(float v0, float v1) {
    uint32_t d;
    asm("cvt.rn.bf16x2.f32 %0, %1, %2;" : "=r"(d) : "f"(v1), "f"(v0));
    return d;
}
__device__ __forceinline__ void split2(float v0, float v1, uint32_t& hi, uint32_t& lo) {
    hi = pkbf(v0, v1);
    float h0 = __uint_as_float(hi << 16);
    float h1 = __uint_as_float(hi & 0xFFFF0000u);
    lo = pkbf(v0 - h0, v1 - h1);
}
__device__ __forceinline__ void mma16(float* d, const uint32_t* a, uint32_t b0, uint32_t b1) {
    asm volatile(
        "mma.sync.aligned.m16n8k16.row.col.f32.bf16.bf16.f32 "
        "{%0,%1,%2,%3}, {%4,%5,%6,%7}, {%8,%9}, {%0,%1,%2,%3};"
        : "+f"(d[0]), "+f"(d[1]), "+f"(d[2]), "+f"(d[3])
        : "r"(a[0]), "r"(a[1]), "r"(a[2]), "r"(a[3]), "r"(b0), "r"(b1));
}

// ============================================================
// Prep (one launch): blocks 0..2047 WM (coalesced smem-staged),
// blocks 2048..2303 W1 + scalar zero.
// ============================================================
__global__ void k_prep(const float* __restrict__ W1, const float* __restrict__ WM)
{
    const int tid = threadIdx.x;
    if (blockIdx.x < 2048) {
        __shared__ float raw[1024];
        const int g = blockIdx.x >> 7, s = blockIdx.x & 127;
        const float4* src = (const float4*)(WM + ((size_t)g * HID + s * 64) * NE);
        ((float4*)raw)[tid] = src[tid];          // 4KB coalesced
        __syncthreads();
        uint32_t* base = d_wms + (size_t)g * (128 * WSTG_W) + s * WSTG_W;
#pragma unroll
        for (int j = tid; j < 512; j += 256) {
            const int kp = j >> 4, n = j & 15;
            uint32_t hi, lo;
            split2(raw[kp * 32 + n], raw[kp * 32 + 16 + n], hi, lo);
            base[kp * 24 + n] = hi;
            base[768 + kp * 24 + n] = lo;
        }
    } else {
        const int idx = (blockIdx.x - 2048) * 256 + tid;   // -> 65536
        const int s = idx >> 9, kp = (idx >> 4) & 31, n = idx & 15;
        const int k = s * 64 + kp * 2;
        uint32_t hi, lo;
        split2(W1[(size_t)n * HID + k], W1[(size_t)n * HID + k + 1], hi, lo);
        d_w1s[s * WSTG_W + kp * 24 + n] = hi;
        d_w1s[s * WSTG_W + 768 + kp * 24 + n] = lo;
        if (idx < NG) {
            d_gsum[idx] = 0.f;
            d_msum[idx] = 0.f;
            d_gcount[idx] = 0;
            d_gcur[idx] = 0;
            if (idx == 0) d_done = 0;
        }
    }
}

// ============================================================
// Core GEMM: C[64 tok x 16] = X . W^T, bf16 HMMA 3-term split.
// R10 transfer structure (2 x 92KB superstage slots, 1KB X rows + 24.5KB W)
// with decoupled full/empty mbarrier producer-consumer (no lockstep sync).
// Warp w (0..15): mt = w&3 (m16 tile), kh = w>>2 (k16 quarter of 64-k block).
// ============================================================
__device__ __forceinline__ void gemm_core(char* sm, const char* myrow,
                                          const char* wbase, int tid,
                                          float* red, ull* mbs)
{
    const int w = tid >> 5, lane = tid & 31;
    const int mt = w & 3, kh = w >> 2;
    const int q = lane >> 2, c = lane & 3;
    const uint32_t smb = s2u(sm);
    const uint32_t fb0 = s2u(&mbs[0]), fb1 = s2u(&mbs[1]);
    const uint32_t eb0 = s2u(&mbs[2]), eb1 = s2u(&mbs[3]);

    if (tid == 0) {
        MB_INIT(fb0, 1);  MB_INIT(fb1, 1);
        MB_INIT(eb0, 16); MB_INIT(eb1, 16);   // one arrive per warp
    }
    __syncthreads();

    // prologue: superstages 0, 1
    if (tid < 64) {
        bulkcp(smb + tid * XROW_B, myrow, 1024, fb0);
        bulkcp(smb + SLOT_B + tid * XROW_B, myrow + 1024, 1024, fb1);
    } else if (tid == 64) {
        MB_EXPECT(fb0, TXB);
        bulkcp(smb + W_OFF, wbase, WSUP_B, fb0);
        MB_EXPECT(fb1, TXB);
        bulkcp(smb + SLOT_B + W_OFF, wbase + WSUP_B, WSUP_B, fb1);
    }

    // ---- A fragment offsets (within sub-stage 0; + ss*256) ----
    uint32_t offA[4];
#pragma unroll
    for (int j = 0; j < 4; j++) {
        const int row = mt * 16 + q + (j & 1) * 8;
        const int kp = kh * 8 + c + (j >> 1) * 4;
        offA[j] = row * XROW_B + kp * 8;
    }
    // ---- B fragment offsets (hi; lo = +3072): [nt][b01] ----
    uint32_t offB[2][2];
#pragma unroll
    for (int nt = 0; nt < 2; nt++) {
        const int n = nt * 8 + q;
        offB[nt][0] = W_OFF + ((kh * 8 + c) * 24 + n) * 4;
        offB[nt][1] = W_OFF + ((kh * 8 + c + 4) * 24 + n) * 4;
    }

    float acc[2][4];
#pragma unroll
    for (int nt = 0; nt < 2; nt++)
#pragma unroll
        for (int i = 0; i < 4; i++) acc[nt][i] = 0.f;

    for (int S = 0; S < NSUP; S++) {
        const uint32_t slot = S & 1;
        const uint32_t par = (S >> 1) & 1;
        mb_wait(slot ? fb1 : fb0, par);

        const char* bb = sm + slot * SLOT_B;
#pragma unroll
        for (int ss = 0; ss < 4; ss++) {
            const uint32_t ao = ss * 256, bo = ss * 6144;
            uint32_t ah[4], al[4];
#pragma unroll
            for (int j = 0; j < 4; j++) {
                float2 v = *(const float2*)(bb + offA[j] + ao);
                split2(v.x, v.y, ah[j], al[j]);
            }
#pragma unroll
            for (int nt = 0; nt < 2; nt++) {
                const uint32_t bh0 = *(const uint32_t*)(bb + offB[nt][0] + bo);
                const uint32_t bh1 = *(const uint32_t*)(bb + offB[nt][1] + bo);
                const uint32_t bl0 = *(const uint32_t*)(bb + offB[nt][0] + bo + 3072);
                const uint32_t bl1 = *(const uint32_t*)(bb + offB[nt][1] + bo + 3072);
                mma16(acc[nt], ah, bh0, bh1);   // ah*bh
                mma16(acc[nt], ah, bl0, bl1);   // ah*bl
                mma16(acc[nt], al, bh0, bh1);   // al*bh  (al*bl dropped)
            }
        }
        // all LDS of this slot are consumed by HMMA before this issues
        if (lane == 0) MB_ARRIVE(slot ? eb1 : eb0);

        // producers: wait for drain, reissue slot for S+2 (warps 0-2 only)
        if (S + 2 < NSUP && tid < 96) {
            mb_wait(slot ? eb1 : eb0, par);
            if (tid < 64) {
                bulkcp(smb + slot * SLOT_B + tid * XROW_B,
                       myrow + (size_t)(S + 2) * 1024, 1024, slot ? fb1 : fb0);
            } else if (tid == 64) {
                MB_EXPECT(slot ? fb1 : fb0, TXB);
                bulkcp(smb + slot * SLOT_B + W_OFF,
                       wbase + (size_t)(S + 2) * WSUP_B, WSUP_B, slot ? fb1 : fb0);
            }
        }
    }
    __syncthreads();   // all warps done consuming before smem reuse

    // ---- cross-kh reduction (4 slices) into red[64][17] ----
    for (int step = 0; step < 4; step++) {
        if (kh == step) {
#pragma unroll
            for (int nt = 0; nt < 2; nt++) {
                const int r0 = mt * 16 + q, cc = nt * 8 + 2 * c;
                if (step == 0) {
                    red[r0 * 17 + cc]           = acc[nt][0];
                    red[r0 * 17 + cc + 1]       = acc[nt][1];
                    red[(r0 + 8) * 17 + cc]     = acc[nt][2];
                    red[(r0 + 8) * 17 + cc + 1] = acc[nt][3];
                } else {
                    red[r0 * 17 + cc]           += acc[nt][0];
                    red[r0 * 17 + cc + 1]       += acc[nt][1];
                    red[(r0 + 8) * 17 + cc]     += acc[nt][2];
                    red[(r0 + 8) * 17 + cc + 1] += acc[nt][3];
                }
            }
        }
        __syncthreads();
    }
}

// ============================================================
// Kernel 1: group-gate GEMM + softmax/argmax/sums/hist
// ============================================================
__global__ void __launch_bounds__(NTHR, 1)
k_gemm1(const float* __restrict__ X)
{
    extern __shared__ __align__(16) char sm[];
    __shared__ ull mbs[4];
    __shared__ int shist[NG];
    const int tid = threadIdx.x;
    if (tid < NG) shist[tid] = 0;

    const char* myrow = (const char*)(X + (size_t)(blockIdx.x * BM + (tid & 63)) * HID);
    float* red = (float*)sm;
    gemm_core(sm, myrow, (const char*)d_w1s, tid, red, mbs);

    float* pb = (float*)(sm + 4608);   // [64][17]
    if (tid < BM) {
        float lg[NG];
#pragma unroll
        for (int g = 0; g < NG; g++) lg[g] = red[tid * 17 + g];
        float mx = lg[0];
        int gi = 0;
#pragma unroll
        for (int g = 1; g < NG; g++)
            if (lg[g] > mx) { mx = lg[g]; gi = g; }
        float p[NG], ss = 0.f;
#pragma unroll
        for (int g = 0; g < NG; g++) { p[g] = __expf(lg[g] - mx); ss += p[g]; }
        const float inv = 1.0f / ss;
#pragma unroll
        for (int g = 0; g < NG; g++) pb[tid * 17 + g] = p[g] * inv;
        d_gsel[blockIdx.x * BM + tid] = gi;
        atomicAdd(&shist[gi], 1);
    }
    __syncthreads();
    if (tid < NG) {
        float s = 0.f;
        for (int t = 0; t < BM; t++) s += pb[t * 17 + tid];
        atomicAdd(&d_gsum[tid], s);
        atomicAdd(&d_gcount[tid], shist[tid]);
    }
}

// ============================================================
// Scatter with local prefix
// ============================================================
__global__ void k_scatter()
{
    __shared__ int cnt[NG], base[NG];
    const int tid = threadIdx.x;
    if (tid < NG) cnt[tid] = 0;
    __syncthreads();
    const int n = blockIdx.x * blockDim.x + tid;
    const int g = d_gsel[n];
    const int rr = atomicAdd(&cnt[g], 1);
    __syncthreads();
    if (tid < NG) {
        int goff = 0;
        for (int h = 0; h < NG; h++)
            if (h < tid) goff += d_gcount[h];
        base[tid] = goff + atomicAdd(&d_gcur[tid], cnt[tid]);
    }
    __syncthreads();
    d_perm[base[g] + rr] = n;
}

// ============================================================
// Kernel 2: mini-gate GEMM (gathered rows) + top-4 + aux finalize
// ============================================================
__device__ __forceinline__ void tick_final(float* out, int out_size, int nblk)
{
    __threadfence();
    const int t = atomicAdd(&d_done, 1);
    if (t == nblk - 1) {
        __threadfence();
        float a = 0.f;
        for (int i = 0; i < NG; i++) { float x = d_gsum[i] / (float)N_TOK; a += x * x; }
        for (int i = 0; i < NE; i++) { float x = d_msum[i] / (float)N_TOK; a += x * x; }
        out[out_size - 1] = a;
    }
}

__global__ void __launch_bounds__(NTHR, 1)
k_gemm2(const float* __restrict__ X, float* __restrict__ out, int out_size)
{
    const int g = blockIdx.y;
    const int cnt = d_gcount[g];
    const int start = blockIdx.x * BM;
    const int nblk = gridDim.x * gridDim.y;
    const int tid = threadIdx.x;
    if (start >= cnt) {
        if (tid == 0) tick_final(out, out_size, nblk);
        return;
    }
    const int nvalid = min(BM, cnt - start);

    extern __shared__ __align__(16) char sm[];
    __shared__ ull mbs[4];
    __shared__ int rows_s[BM];
    if (tid == 0) {            // local prefix: offset of group g
        int off = 0;
        for (int h = 0; h < NG; h++)
            if (h < g) off += d_gcount[h];
        rows_s[0] = off;       // temp
    }
    __syncthreads();
    const int off = rows_s[0];
    __syncthreads();
    if (tid < BM) {
        int ix = start + tid;
        if (ix >= cnt) ix = cnt - 1;   // clamp: duplicate rows, discarded
        rows_s[tid] = d_perm[off + ix];
    }
    __syncthreads();

    const char* myrow = (const char*)(X + (size_t)rows_s[tid & 63] * HID);
    const char* wbase = (const char*)(d_wms + (size_t)g * (128 * WSTG_W));
    float* red = (float*)sm;
    gemm_core(sm, myrow, wbase, tid, red, mbs);

    float* pb = (float*)(sm + 4608);   // [64][17]
    if (tid < BM) {
        const bool valid = (tid < nvalid);
        float lg[NE];
#pragma unroll
        for (int e = 0; e < NE; e++) lg[e] = red[tid * 17 + e];
        float mx = lg[0];
#pragma unroll
        for (int e = 1; e < NE; e++) mx = fmaxf(mx, lg[e]);
        float ex[NE], ss = 0.f;
#pragma unroll
        for (int e = 0; e < NE; e++) { ex[e] = __expf(lg[e] - mx); ss += ex[e]; }
        const float inv = 1.0f / ss;
#pragma unroll
        for (int e = 0; e < NE; e++) pb[tid * 17 + e] = valid ? ex[e] * inv : 0.f;

        if (valid) {
            // top-4 by logit; strict > keeps lowest index on ties (lax.top_k order)
            float cur[NE];
#pragma unroll
            for (int e = 0; e < NE; e++) cur[e] = lg[e];
            int eidx[4];
            float ev[4], den = 0.f;
#pragma unroll
            for (int j = 0; j < 4; j++) {
                float best = -3.4e38f;
                int bi = 0;
#pragma unroll
                for (int e = 0; e < NE; e++)
                    if (cur[e] > best) { best = cur[e]; bi = e; }
                cur[bi] = -3.4e38f;
                eidx[j] = bi;
                ev[j] = ex[bi];
                den += ex[bi];
            }
            // group prob cancels in normalization: final = ex_j / sum(top4 ex)
            const float invd = 1.0f / den;
            const int n = rows_s[tid];
#pragma unroll
            for (int j = 0; j < 4; j++) {
                out[(size_t)n * 4 + j] = ev[j] * invd;
                out[(size_t)N_TOK * 4 + (size_t)n * 4 + j] = (float)(g * NE + eidx[j]);
            }
        }
    }
    __syncthreads();
    if (tid < NE) {
        float s = 0.f;
        for (int t = 0; t < BM; t++) s += pb[t * 17 + tid];
        atomicAdd(&d_msum[tid], s);
    }
    __syncthreads();
    if (tid == 0) tick_final(out, out_size, nblk);
}

// ============================================================
extern "C" void kernel_launch(void* const* d_in, const int* in_sizes, int n_in,
                              void* d_out, int out_size)
{
    const float* X  = (const float*)d_in[0];  // hidden_states [N, H]
    const float* W1 = (const float*)d_in[1];  // group_gate_w  [16, H]
    const float* WM = (const float*)d_in[2];  // mini_gates    [16, H, 16]
    float* out = (float*)d_out;               // [probs N*4 | indices N*4 | aux]

    cudaFuncSetAttribute(k_gemm1, cudaFuncAttributeMaxDynamicSharedMemorySize, SMEM_DYN);
    cudaFuncSetAttribute(k_gemm2, cudaFuncAttributeMaxDynamicSharedMemorySize, SMEM_DYN);

    k_prep<<<2304, 256>>>(W1, WM);                                        // launch 1
    k_gemm1<<<N_TOK / BM, NTHR, SMEM_DYN>>>(X);                           // launch 2
    k_scatter<<<N_TOK / 256, 256>>>();                                    // launch 3
    k_gemm2<<<dim3(N_TOK / BM, NG), NTHR, SMEM_DYN>>>(X, out, out_size);  // launch 4 (ncu slot)
}

// round 16
// speedup vs baseline: 2.3036x; 1.0237x over previous
#include <cuda_runtime.h>
#include <cstdint>

#define N_TOK 8192
#define HID   8192
#define NG    16
#define NE    16

#define BM     64
#define NTHR   512
#define NSUP   32                 // superstages of 256 k
#define XROW_B 1056               // padded X row stride (word off ≡ 8 mod 32)
#define W_OFF  (64 * XROW_B)      // 67584
#define WSUP_B 24576              // W bytes per superstage (4 x 6144)
#define SLOT_B (W_OFF + WSUP_B)   // 92160
#define SMEM_DYN (2 * SLOT_B)     // 184320
#define TXB    (64 * 1024 + WSUP_B)  // 90112
#define WSTG_W 1536               // W words per 64-k block (hi 768 + lo 768, rows padded 24)

typedef unsigned long long ull;

// ---------------- device scratch ----------------
__device__ uint32_t d_w1s[128 * WSTG_W];
__device__ uint32_t d_wms[NG * 128 * WSTG_W];      // 12.6MB
__device__ float d_gsum[NG];
__device__ float d_msum[NE];
__device__ int   d_gsel[N_TOK];
__device__ int   d_gcount[NG];
__device__ int   d_gcur[NG];
__device__ int   d_perm[N_TOK];
__device__ int   d_done;

// ---------------- helpers ----------------
__device__ __forceinline__ uint32_t s2u(const void* p) {
    return (uint32_t)__cvta_generic_to_shared(p);
}
__device__ __forceinline__ void bulkcp(uint32_t dst, const void* src, uint32_t n, uint32_t mbar) {
    asm volatile(
        "cp.async.bulk.shared::cluster.global.mbarrier::complete_tx::bytes [%0], [%1], %2, [%3];"
        :: "r"(dst), "l"(src), "r"(n), "r"(mbar) : "memory");
}
#define MB_INIT(a, c) asm volatile("mbarrier.init.shared.b64 [%0], %1;" :: "r"(a), "r"(c) : "memory")
#define MB_EXPECT(a, tx) asm volatile("mbarrier.arrive.expect_tx.shared.b64 _, [%0], %1;" :: "r"(a), "r"(tx) : "memory")
__device__ __forceinline__ void mb_wait(uint32_t mb, uint32_t parity) {
    asm volatile(
        "{\n\t.reg .pred P;\n\t"
        "WL_%=:\n\t"
        "mbarrier.try_wait.parity.acquire.cta.shared::cta.b64 P, [%0], %1, 0x989680;\n\t"
        "@P bra.uni WD_%=;\n\t"
        "bra.uni WL_%=;\n\t"
        "WD_%=:\n\t}"
        :: "r"(mb), "r"(parity) : "memory");
}
__device__ __forceinline__ uint32_t pkbf(float v0, float v1) {
    uint32_t d;
    asm("cvt.rn.bf16x2.f32 %0, %1, %2;" : "=r"(d) : "f"(v1), "f"(v0));
    return d;
}
__device__ __forceinline__ void split2(float v0, float v1, uint32_t& hi, uint32_t& lo) {
    hi = pkbf(v0, v1);
    float h0 = __uint_as_float(hi << 16);
    float h1 = __uint_as_float(hi & 0xFFFF0000u);
    lo = pkbf(v0 - h0, v1 - h1);
}
__device__ __forceinline__ void mma16(float* d, const uint32_t* a, uint32_t b0, uint32_t b1) {
    asm volatile(
        "mma.sync.aligned.m16n8k16.row.col.f32.bf16.bf16.f32 "
        "{%0,%1,%2,%3}, {%4,%5,%6,%7}, {%8,%9}, {%0,%1,%2,%3};"
        : "+f"(d[0]), "+f"(d[1]), "+f"(d[2]), "+f"(d[3])
        : "r"(a[0]), "r"(a[1]), "r"(a[2]), "r"(a[3]), "r"(b0), "r"(b1));
}

// ============================================================
// Prep (one launch): blocks 0..2047 WM (coalesced smem-staged),
// blocks 2048..2303 W1 + scalar zero.   [proven in R13]
// ============================================================
__global__ void k_prep(const float* __restrict__ W1, const float* __restrict__ WM)
{
    const int tid = threadIdx.x;
    if (blockIdx.x < 2048) {
        __shared__ float raw[1024];
        const int g = blockIdx.x >> 7, s = blockIdx.x & 127;
        const float4* src = (const float4*)(WM + ((size_t)g * HID + s * 64) * NE);
        ((float4*)raw)[tid] = src[tid];          // 4KB coalesced
        __syncthreads();
        uint32_t* base = d_wms + (size_t)g * (128 * WSTG_W) + s * WSTG_W;
#pragma unroll
        for (int j = tid; j < 512; j += 256) {
            const int kp = j >> 4, n = j & 15;
            uint32_t hi, lo;
            split2(raw[kp * 32 + n], raw[kp * 32 + 16 + n], hi, lo);
            base[kp * 24 + n] = hi;
            base[768 + kp * 24 + n] = lo;
        }
    } else {
        const int idx = (blockIdx.x - 2048) * 256 + tid;   // -> 65536
        const int s = idx >> 9, kp = (idx >> 4) & 31, n = idx & 15;
        const int k = s * 64 + kp * 2;
        uint32_t hi, lo;
        split2(W1[(size_t)n * HID + k], W1[(size_t)n * HID + k + 1], hi, lo);
        d_w1s[s * WSTG_W + kp * 24 + n] = hi;
        d_w1s[s * WSTG_W + 768 + kp * 24 + n] = lo;
        if (idx < NG) {
            d_gsum[idx] = 0.f;
            d_msum[idx] = 0.f;
            d_gcount[idx] = 0;
            d_gcur[idx] = 0;
            if (idx == 0) d_done = 0;
        }
    }
}

// ============================================================
// Core GEMM [proven R10]: C[64 tok x 16] = X . W^T, bf16 HMMA 3-term,
// bulk-copy double-buffered superstages (256 k each).
// Warp w (0..15): mt = w&3 (m16 tile), kh = w>>2 (k16 quarter of 64-k block).
// ============================================================
__device__ __forceinline__ void gemm_core(char* sm, const char* myrow,
                                          const char* wbase, int tid,
                                          float* red, ull* mbs)
{
    const int w = tid >> 5, lane = tid & 31;
    const int mt = w & 3, kh = w >> 2;
    const int q = lane >> 2, c = lane & 3;
    const uint32_t smb = s2u(sm);
    const uint32_t fb0 = s2u(&mbs[0]), fb1 = s2u(&mbs[1]);

    if (tid == 0) { MB_INIT(fb0, 1); MB_INIT(fb1, 1); }
    __syncthreads();

    // prologue: superstages 0, 1
    if (tid < 64) {
        bulkcp(smb + tid * XROW_B, myrow, 1024, fb0);
        bulkcp(smb + SLOT_B + tid * XROW_B, myrow + 1024, 1024, fb1);
    } else if (tid == 64) {
        MB_EXPECT(fb0, TXB);
        bulkcp(smb + W_OFF, wbase, WSUP_B, fb0);
        MB_EXPECT(fb1, TXB);
        bulkcp(smb + SLOT_B + W_OFF, wbase + WSUP_B, WSUP_B, fb1);
    }

    // ---- A fragment offsets (within sub-stage 0; + ss*256) ----
    uint32_t offA[4];
#pragma unroll
    for (int j = 0; j < 4; j++) {
        const int row = mt * 16 + q + (j & 1) * 8;
        const int kp = kh * 8 + c + (j >> 1) * 4;
        offA[j] = row * XROW_B + kp * 8;
    }
    // ---- B fragment offsets (hi; lo = +3072): [nt][b01] ----
    uint32_t offB[2][2];
#pragma unroll
    for (int nt = 0; nt < 2; nt++) {
        const int n = nt * 8 + q;
        offB[nt][0] = W_OFF + ((kh * 8 + c) * 24 + n) * 4;
        offB[nt][1] = W_OFF + ((kh * 8 + c + 4) * 24 + n) * 4;
    }

    float acc[2][4];
#pragma unroll
    for (int nt = 0; nt < 2; nt++)
#pragma unroll
        for (int i = 0; i < 4; i++) acc[nt][i] = 0.f;

    for (int S = 0; S < NSUP; S++) {
        const uint32_t slot = S & 1;
        mb_wait(slot ? fb1 : fb0, (S >> 1) & 1);

        const char* bb = sm + slot * SLOT_B;
#pragma unroll
        for (int ss = 0; ss < 4; ss++) {
            const uint32_t ao = ss * 256, bo = ss * 6144;
            uint32_t ah[4], al[4];
#pragma unroll
            for (int j = 0; j < 4; j++) {
                float2 v = *(const float2*)(bb + offA[j] + ao);
                split2(v.x, v.y, ah[j], al[j]);
            }
#pragma unroll
            for (int nt = 0; nt < 2; nt++) {
                const uint32_t bh0 = *(const uint32_t*)(bb + offB[nt][0] + bo);
                const uint32_t bh1 = *(const uint32_t*)(bb + offB[nt][1] + bo);
                const uint32_t bl0 = *(const uint32_t*)(bb + offB[nt][0] + bo + 3072);
                const uint32_t bl1 = *(const uint32_t*)(bb + offB[nt][1] + bo + 3072);
                mma16(acc[nt], ah, bh0, bh1);   // ah*bh
                mma16(acc[nt], ah, bl0, bl1);   // ah*bl
                mma16(acc[nt], al, bh0, bh1);   // al*bh  (al*bl dropped)
            }
        }
        __syncthreads();        // slot fully consumed by all threads
        if (S + 2 < NSUP) {
            const uint32_t fbn = slot ? fb1 : fb0;
            if (tid < 64) {
                bulkcp(smb + slot * SLOT_B + tid * XROW_B,
                       myrow + (size_t)(S + 2) * 1024, 1024, fbn);
            } else if (tid == 64) {
                MB_EXPECT(fbn, TXB);
                bulkcp(smb + slot * SLOT_B + W_OFF,
                       wbase + (size_t)(S + 2) * WSUP_B, WSUP_B, fbn);
            }
        }
    }

    // ---- cross-kh reduction (4 slices) into red[64][17] ----
    for (int step = 0; step < 4; step++) {
        if (kh == step) {
#pragma unroll
            for (int nt = 0; nt < 2; nt++) {
                const int r0 = mt * 16 + q, cc = nt * 8 + 2 * c;
                if (step == 0) {
                    red[r0 * 17 + cc]           = acc[nt][0];
                    red[r0 * 17 + cc + 1]       = acc[nt][1];
                    red[(r0 + 8) * 17 + cc]     = acc[nt][2];
                    red[(r0 + 8) * 17 + cc + 1] = acc[nt][3];
                } else {
                    red[r0 * 17 + cc]           += acc[nt][0];
                    red[r0 * 17 + cc + 1]       += acc[nt][1];
                    red[(r0 + 8) * 17 + cc]     += acc[nt][2];
                    red[(r0 + 8) * 17 + cc + 1] += acc[nt][3];
                }
            }
        }
        __syncthreads();
    }
}

// ============================================================
// Kernel 1: group-gate GEMM + softmax/argmax/sums/hist
// ============================================================
__global__ void __launch_bounds__(NTHR, 1)
k_gemm1(const float* __restrict__ X)
{
    extern __shared__ __align__(16) char sm[];
    __shared__ ull mbs[2];
    __shared__ int shist[NG];
    const int tid = threadIdx.x;
    if (tid < NG) shist[tid] = 0;

    const char* myrow = (const char*)(X + (size_t)(blockIdx.x * BM + (tid & 63)) * HID);
    float* red = (float*)sm;
    gemm_core(sm, myrow, (const char*)d_w1s, tid, red, mbs);

    float* pb = (float*)(sm + 4608);   // [64][17]
    if (tid < BM) {
        float lg[NG];
#pragma unroll
        for (int g = 0; g < NG; g++) lg[g] = red[tid * 17 + g];
        float mx = lg[0];
        int gi = 0;
#pragma unroll
        for (int g = 1; g < NG; g++)
            if (lg[g] > mx) { mx = lg[g]; gi = g; }
        float p[NG], ss = 0.f;
#pragma unroll
        for (int g = 0; g < NG; g++) { p[g] = __expf(lg[g] - mx); ss += p[g]; }
        const float inv = 1.0f / ss;
#pragma unroll
        for (int g = 0; g < NG; g++) pb[tid * 17 + g] = p[g] * inv;
        d_gsel[blockIdx.x * BM + tid] = gi;
        atomicAdd(&shist[gi], 1);
    }
    __syncthreads();
    if (tid < NG) {
        float s = 0.f;
        for (int t = 0; t < BM; t++) s += pb[t * 17 + tid];
        atomicAdd(&d_gsum[tid], s);
        atomicAdd(&d_gcount[tid], shist[tid]);
    }
}

// ============================================================
// Scatter with local prefix  [proven since R7]
// ============================================================
__global__ void k_scatter()
{
    __shared__ int cnt[NG], base[NG];
    const int tid = threadIdx.x;
    if (tid < NG) cnt[tid] = 0;
    __syncthreads();
    const int n = blockIdx.x * blockDim.x + tid;
    const int g = d_gsel[n];
    const int rr = atomicAdd(&cnt[g], 1);
    __syncthreads();
    if (tid < NG) {
        int goff = 0;
        for (int h = 0; h < NG; h++)
            if (h < tid) goff += d_gcount[h];
        base[tid] = goff + atomicAdd(&d_gcur[tid], cnt[tid]);
    }
    __syncthreads();
    d_perm[base[g] + rr] = n;
}

// ============================================================
// Kernel 2: mini-gate GEMM (gathered rows) + top-4 + fused aux finalize
// ============================================================
__device__ __forceinline__ void tick_final(float* out, int out_size, int nblk)
{
    __threadfence();
    const int t = atomicAdd(&d_done, 1);
    if (t == nblk - 1) {
        __threadfence();
        float a = 0.f;
        for (int i = 0; i < NG; i++) { float x = d_gsum[i] / (float)N_TOK; a += x * x; }
        for (int i = 0; i < NE; i++) { float x = d_msum[i] / (float)N_TOK; a += x * x; }
        out[out_size - 1] = a;
    }
}

__global__ void __launch_bounds__(NTHR, 1)
k_gemm2(const float* __restrict__ X, float* __restrict__ out, int out_size)
{
    const int g = blockIdx.y;
    const int cnt = d_gcount[g];
    const int start = blockIdx.x * BM;
    const int nblk = gridDim.x * gridDim.y;
    const int tid = threadIdx.x;
    if (start >= cnt) {
        if (tid == 0) tick_final(out, out_size, nblk);
        return;
    }
    const int nvalid = min(BM, cnt - start);

    extern __shared__ __align__(16) char sm[];
    __shared__ ull mbs[2];
    __shared__ int rows_s[BM];
    if (tid == 0) {            // local prefix: offset of group g
        int off = 0;
        for (int h = 0; h < NG; h++)
            if (h < g) off += d_gcount[h];
        rows_s[0] = off;       // temp
    }
    __syncthreads();
    const int off = rows_s[0];
    __syncthreads();
    if (tid < BM) {
        int ix = start + tid;
        if (ix >= cnt) ix = cnt - 1;   // clamp: duplicate rows, discarded
        rows_s[tid] = d_perm[off + ix];
    }
    __syncthreads();

    const char* myrow = (const char*)(X + (size_t)rows_s[tid & 63] * HID);
    const char* wbase = (const char*)(d_wms + (size_t)g * (128 * WSTG_W));
    float* red = (float*)sm;
    gemm_core(sm, myrow, wbase, tid, red, mbs);

    float* pb = (float*)(sm + 4608);   // [64][17]
    if (tid < BM) {
        const bool valid = (tid < nvalid);
        float lg[NE];
#pragma unroll
        for (int e = 0; e < NE; e++) lg[e] = red[tid * 17 + e];
        float mx = lg[0];
#pragma unroll
        for (int e = 1; e < NE; e++) mx = fmaxf(mx, lg[e]);
        float ex[NE], ss = 0.f;
#pragma unroll
        for (int e = 0; e < NE; e++) { ex[e] = __expf(lg[e] - mx); ss += ex[e]; }
        const float inv = 1.0f / ss;
#pragma unroll
        for (int e = 0; e < NE; e++) pb[tid * 17 + e] = valid ? ex[e] * inv : 0.f;

        if (valid) {
            // top-4 by logit; strict > keeps lowest index on ties (lax.top_k order)
            float cur[NE];
#pragma unroll
            for (int e = 0; e < NE; e++) cur[e] = lg[e];
            int eidx[4];
            float ev[4], den = 0.f;
#pragma unroll
            for (int j = 0; j < 4; j++) {
                float best = -3.4e38f;
                int bi = 0;
#pragma unroll
                for (int e = 0; e < NE; e++)
                    if (cur[e] > best) { best = cur[e]; bi = e; }
                cur[bi] = -3.4e38f;
                eidx[j] = bi;
                ev[j] = ex[bi];
                den += ex[bi];
            }
            // group prob cancels in normalization: final = ex_j / sum(top4 ex)
            const float invd = 1.0f / den;
            const int n = rows_s[tid];
#pragma unroll
            for (int j = 0; j < 4; j++) {
                out[(size_t)n * 4 + j] = ev[j] * invd;
                out[(size_t)N_TOK * 4 + (size_t)n * 4 + j] = (float)(g * NE + eidx[j]);
            }
        }
    }
    __syncthreads();
    if (tid < NE) {
        float s = 0.f;
        for (int t = 0; t < BM; t++) s += pb[t * 17 + tid];
        atomicAdd(&d_msum[tid], s);
    }
    __syncthreads();
    if (tid == 0) tick_final(out, out_size, nblk);
}

// ============================================================
extern "C" void kernel_launch(void* const* d_in, const int* in_sizes, int n_in,
                              void* d_out, int out_size)
{
    const float* X  = (const float*)d_in[0];  // hidden_states [N, H]
    const float* W1 = (const float*)d_in[1];  // group_gate_w  [16, H]
    const float* WM = (const float*)d_in[2];  // mini_gates    [16, H, 16]
    float* out = (float*)d_out;               // [probs N*4 | indices N*4 | aux]

    cudaFuncSetAttribute(k_gemm1, cudaFuncAttributeMaxDynamicSharedMemorySize, SMEM_DYN);
    cudaFuncSetAttribute(k_gemm2, cudaFuncAttributeMaxDynamicSharedMemorySize, SMEM_DYN);

    k_prep<<<2304, 256>>>(W1, WM);                                        // launch 1
    k_gemm1<<<N_TOK / BM, NTHR, SMEM_DYN>>>(X);                           // launch 2
    k_scatter<<<N_TOK / 256, 256>>>();                                    // launch 3
    k_gemm2<<<dim3(N_TOK / BM, NG), NTHR, SMEM_DYN>>>(X, out, out_size);  // launch 4
}

// round 17
// speedup vs baseline: 2.7186x; 1.1802x over previous
#include <cuda_runtime.h>
#include <cstdint>

#define N_TOK 8192
#define HID   8192
#define NG    16
#define NE    16

#define BM     64
#define NTHR   512
#define NSUP   32                 // superstages of 256 k
#define XROW_B 1056               // padded X row stride (word off ≡ 8 mod 32)
#define W_OFF  (64 * XROW_B)      // 67584
#define WSUP_B 24576              // W bytes per superstage (4 x 6144)
#define SLOT_B (W_OFF + WSUP_B)   // 92160
#define SMEM_DYN (2 * SLOT_B)     // 184320
#define TXB    (64 * 1024 + WSUP_B)  // 90112
#define WSTG_W 1536               // W words per 64-k block (hi 768 + lo 768, rows padded 24)
#define MAXBLK 144                // sum ceil(cnt_g/64) <= 128 + 16

typedef unsigned long long ull;

// ---------------- device scratch ----------------
__device__ uint32_t d_w1s[128 * WSTG_W];
__device__ uint32_t d_wms[NG * 128 * WSTG_W];      // 12.6MB
__device__ float d_gsum[NG];
__device__ float d_msum[NE];
__device__ int   d_gsel[N_TOK];
__device__ int   d_gcount[NG];
__device__ int   d_gcur[NG];
__device__ int   d_perm[N_TOK];
__device__ int   d_sched[MAXBLK];  // (g<<26)|(start<<13)|perm_off
__device__ int   d_sched_n;

// ---------------- helpers ----------------
__device__ __forceinline__ uint32_t s2u(const void* p) {
    return (uint32_t)__cvta_generic_to_shared(p);
}
__device__ __forceinline__ void bulkcp(uint32_t dst, const void* src, uint32_t n, uint32_t mbar) {
    asm volatile(
        "cp.async.bulk.shared::cluster.global.mbarrier::complete_tx::bytes [%0], [%1], %2, [%3];"
        :: "r"(dst), "l"(src), "r"(n), "r"(mbar) : "memory");
}
#define MB_INIT(a, c) asm volatile("mbarrier.init.shared.b64 [%0], %1;" :: "r"(a), "r"(c) : "memory")
#define MB_EXPECT(a, tx) asm volatile("mbarrier.arrive.expect_tx.shared.b64 _, [%0], %1;" :: "r"(a), "r"(tx) : "memory")
__device__ __forceinline__ void mb_wait(uint32_t mb, uint32_t parity) {
    asm volatile(
        "{\n\t.reg .pred P;\n\t"
        "WL_%=:\n\t"
        "mbarrier.try_wait.parity.acquire.cta.shared::cta.b64 P, [%0], %1, 0x989680;\n\t"
        "@P bra.uni WD_%=;\n\t"
        "bra.uni WL_%=;\n\t"
        "WD_%=:\n\t}"
        :: "r"(mb), "r"(parity) : "memory");
}
__device__ __forceinline__ uint32_t pkbf(float v0, float v1) {
    uint32_t d;
    asm("cvt.rn.bf16x2.f32 %0, %1, %2;" : "=r"(d) : "f"(v1), "f"(v0));
    return d;
}
__device__ __forceinline__ void split2(float v0, float v1, uint32_t& hi, uint32_t& lo) {
    hi = pkbf(v0, v1);
    float h0 = __uint_as_float(hi << 16);
    float h1 = __uint_as_float(hi & 0xFFFF0000u);
    lo = pkbf(v0 - h0, v1 - h1);
}
__device__ __forceinline__ void mma16(float* d, const uint32_t* a, uint32_t b0, uint32_t b1) {
    asm volatile(
        "mma.sync.aligned.m16n8k16.row.col.f32.bf16.bf16.f32 "
        "{%0,%1,%2,%3}, {%4,%5,%6,%7}, {%8,%9}, {%0,%1,%2,%3};"
        : "+f"(d[0]), "+f"(d[1]), "+f"(d[2]), "+f"(d[3])
        : "r"(a[0]), "r"(a[1]), "r"(a[2]), "r"(a[3]), "r"(b0), "r"(b1));
}

// ============================================================
// Prep (one launch): blocks 0..2047 WM (coalesced smem-staged),
// blocks 2048..2303 W1 + scalar zero.   [proven R16]
// ============================================================
__global__ void k_prep(const float* __restrict__ W1, const float* __restrict__ WM)
{
    const int tid = threadIdx.x;
    if (blockIdx.x < 2048) {
        __shared__ float raw[1024];
        const int g = blockIdx.x >> 7, s = blockIdx.x & 127;
        const float4* src = (const float4*)(WM + ((size_t)g * HID + s * 64) * NE);
        ((float4*)raw)[tid] = src[tid];          // 4KB coalesced
        __syncthreads();
        uint32_t* base = d_wms + (size_t)g * (128 * WSTG_W) + s * WSTG_W;
#pragma unroll
        for (int j = tid; j < 512; j += 256) {
            const int kp = j >> 4, n = j & 15;
            uint32_t hi, lo;
            split2(raw[kp * 32 + n], raw[kp * 32 + 16 + n], hi, lo);
            base[kp * 24 + n] = hi;
            base[768 + kp * 24 + n] = lo;
        }
    } else {
        const int idx = (blockIdx.x - 2048) * 256 + tid;   // -> 65536
        const int s = idx >> 9, kp = (idx >> 4) & 31, n = idx & 15;
        const int k = s * 64 + kp * 2;
        uint32_t hi, lo;
        split2(W1[(size_t)n * HID + k], W1[(size_t)n * HID + k + 1], hi, lo);
        d_w1s[s * WSTG_W + kp * 24 + n] = hi;
        d_w1s[s * WSTG_W + 768 + kp * 24 + n] = lo;
        if (idx < NG) {
            d_gsum[idx] = 0.f;
            d_msum[idx] = 0.f;
            d_gcount[idx] = 0;
            d_gcur[idx] = 0;
        }
    }
}

// ============================================================
// Core GEMM [proven R10]: C[64 tok x 16] = X . W^T, bf16 HMMA 3-term,
// bulk-copy double-buffered superstages (256 k each).
// Warp w (0..15): mt = w&3 (m16 tile), kh = w>>2 (k16 quarter of 64-k block).
// ============================================================
__device__ __forceinline__ void gemm_core(char* sm, const char* myrow,
                                          const char* wbase, int tid,
                                          float* red, ull* mbs)
{
    const int w = tid >> 5, lane = tid & 31;
    const int mt = w & 3, kh = w >> 2;
    const int q = lane >> 2, c = lane & 3;
    const uint32_t smb = s2u(sm);
    const uint32_t fb0 = s2u(&mbs[0]), fb1 = s2u(&mbs[1]);

    if (tid == 0) { MB_INIT(fb0, 1); MB_INIT(fb1, 1); }
    __syncthreads();

    // prologue: superstages 0, 1
    if (tid < 64) {
        bulkcp(smb + tid * XROW_B, myrow, 1024, fb0);
        bulkcp(smb + SLOT_B + tid * XROW_B, myrow + 1024, 1024, fb1);
    } else if (tid == 64) {
        MB_EXPECT(fb0, TXB);
        bulkcp(smb + W_OFF, wbase, WSUP_B, fb0);
        MB_EXPECT(fb1, TXB);
        bulkcp(smb + SLOT_B + W_OFF, wbase + WSUP_B, WSUP_B, fb1);
    }

    // ---- A fragment offsets (within sub-stage 0; + ss*256) ----
    uint32_t offA[4];
#pragma unroll
    for (int j = 0; j < 4; j++) {
        const int row = mt * 16 + q + (j & 1) * 8;
        const int kp = kh * 8 + c + (j >> 1) * 4;
        offA[j] = row * XROW_B + kp * 8;
    }
    // ---- B fragment offsets (hi; lo = +3072): [nt][b01] ----
    uint32_t offB[2][2];
#pragma unroll
    for (int nt = 0; nt < 2; nt++) {
        const int n = nt * 8 + q;
        offB[nt][0] = W_OFF + ((kh * 8 + c) * 24 + n) * 4;
        offB[nt][1] = W_OFF + ((kh * 8 + c + 4) * 24 + n) * 4;
    }

    float acc[2][4];
#pragma unroll
    for (int nt = 0; nt < 2; nt++)
#pragma unroll
        for (int i = 0; i < 4; i++) acc[nt][i] = 0.f;

    for (int S = 0; S < NSUP; S++) {
        const uint32_t slot = S & 1;
        mb_wait(slot ? fb1 : fb0, (S >> 1) & 1);

        const char* bb = sm + slot * SLOT_B;
#pragma unroll
        for (int ss = 0; ss < 4; ss++) {
            const uint32_t ao = ss * 256, bo = ss * 6144;
            uint32_t ah[4], al[4];
#pragma unroll
            for (int j = 0; j < 4; j++) {
                float2 v = *(const float2*)(bb + offA[j] + ao);
                split2(v.x, v.y, ah[j], al[j]);
            }
#pragma unroll
            for (int nt = 0; nt < 2; nt++) {
                const uint32_t bh0 = *(const uint32_t*)(bb + offB[nt][0] + bo);
                const uint32_t bh1 = *(const uint32_t*)(bb + offB[nt][1] + bo);
                const uint32_t bl0 = *(const uint32_t*)(bb + offB[nt][0] + bo + 3072);
                const uint32_t bl1 = *(const uint32_t*)(bb + offB[nt][1] + bo + 3072);
                mma16(acc[nt], ah, bh0, bh1);   // ah*bh
                mma16(acc[nt], ah, bl0, bl1);   // ah*bl
                mma16(acc[nt], al, bh0, bh1);   // al*bh  (al*bl dropped)
            }
        }
        __syncthreads();        // slot fully consumed by all threads
        if (S + 2 < NSUP) {
            const uint32_t fbn = slot ? fb1 : fb0;
            if (tid < 64) {
                bulkcp(smb + slot * SLOT_B + tid * XROW_B,
                       myrow + (size_t)(S + 2) * 1024, 1024, fbn);
            } else if (tid == 64) {
                MB_EXPECT(fbn, TXB);
                bulkcp(smb + slot * SLOT_B + W_OFF,
                       wbase + (size_t)(S + 2) * WSUP_B, WSUP_B, fbn);
            }
        }
    }

    // ---- cross-kh reduction (4 slices) into red[64][17] ----
    for (int step = 0; step < 4; step++) {
        if (kh == step) {
#pragma unroll
            for (int nt = 0; nt < 2; nt++) {
                const int r0 = mt * 16 + q, cc = nt * 8 + 2 * c;
                if (step == 0) {
                    red[r0 * 17 + cc]           = acc[nt][0];
                    red[r0 * 17 + cc + 1]       = acc[nt][1];
                    red[(r0 + 8) * 17 + cc]     = acc[nt][2];
                    red[(r0 + 8) * 17 + cc + 1] = acc[nt][3];
                } else {
                    red[r0 * 17 + cc]           += acc[nt][0];
                    red[r0 * 17 + cc + 1]       += acc[nt][1];
                    red[(r0 + 8) * 17 + cc]     += acc[nt][2];
                    red[(r0 + 8) * 17 + cc + 1] += acc[nt][3];
                }
            }
        }
        __syncthreads();
    }
}

// ============================================================
// Kernel 1: group-gate GEMM + softmax/argmax/sums/hist
// ============================================================
__global__ void __launch_bounds__(NTHR, 1)
k_gemm1(const float* __restrict__ X)
{
    extern __shared__ __align__(16) char sm[];
    __shared__ ull mbs[2];
    __shared__ int shist[NG];
    const int tid = threadIdx.x;
    if (tid < NG) shist[tid] = 0;

    const char* myrow = (const char*)(X + (size_t)(blockIdx.x * BM + (tid & 63)) * HID);
    float* red = (float*)sm;
    gemm_core(sm, myrow, (const char*)d_w1s, tid, red, mbs);

    float* pb = (float*)(sm + 4608);   // [64][17]
    if (tid < BM) {
        float lg[NG];
#pragma unroll
        for (int g = 0; g < NG; g++) lg[g] = red[tid * 17 + g];
        float mx = lg[0];
        int gi = 0;
#pragma unroll
        for (int g = 1; g < NG; g++)
            if (lg[g] > mx) { mx = lg[g]; gi = g; }
        float p[NG], ss = 0.f;
#pragma unroll
        for (int g = 0; g < NG; g++) { p[g] = __expf(lg[g] - mx); ss += p[g]; }
        const float inv = 1.0f / ss;
#pragma unroll
        for (int g = 0; g < NG; g++) pb[tid * 17 + g] = p[g] * inv;
        d_gsel[blockIdx.x * BM + tid] = gi;
        atomicAdd(&shist[gi], 1);
    }
    __syncthreads();
    if (tid < NG) {
        float s = 0.f;
        for (int t = 0; t < BM; t++) s += pb[t * 17 + tid];
        atomicAdd(&d_gsum[tid], s);
        atomicAdd(&d_gcount[tid], shist[tid]);
    }
}

// ============================================================
// Scatter (local prefix) + gemm2 schedule build in block 0
// ============================================================
__global__ void k_scatter()
{
    __shared__ int cnt[NG], base[NG];
    const int tid = threadIdx.x;
    if (tid < NG) cnt[tid] = 0;
    __syncthreads();
    const int n = blockIdx.x * blockDim.x + tid;
    const int g = d_gsel[n];
    const int rr = atomicAdd(&cnt[g], 1);
    __syncthreads();
    if (tid < NG) {
        int goff = 0;
        for (int h = 0; h < NG; h++)
            if (h < tid) goff += d_gcount[h];
        base[tid] = goff + atomicAdd(&d_gcur[tid], cnt[tid]);
    }
    __syncthreads();
    d_perm[base[g] + rr] = n;

    // block 0, thread 0: build exact-size gemm2 schedule
    if (blockIdx.x == 0 && tid == 0) {
        int idx = 0, off = 0;
        for (int h = 0; h < NG; h++) {
            const int c = d_gcount[h];
            for (int st = 0; st < c; st += BM)
                d_sched[idx++] = (h << 26) | (st << 13) | (off + st);
            off += c;
        }
        d_sched_n = idx;
    }
}

// ============================================================
// Kernel 2: mini-gate GEMM (scheduled blocks only) + top-4
// ============================================================
__global__ void __launch_bounds__(NTHR, 1)
k_gemm2(const float* __restrict__ X, float* __restrict__ out)
{
    const int tid = threadIdx.x;
    if (blockIdx.x >= d_sched_n) return;
    const int e  = d_sched[blockIdx.x];
    const int g  = e >> 26;
    const int st = (e >> 13) & 8191;
    const int p  = e & 8191;
    const int nvalid = min(BM, d_gcount[g] - st);

    extern __shared__ __align__(16) char sm[];
    __shared__ ull mbs[2];
    __shared__ int rows_s[BM];
    if (tid < BM) {
        int ix = tid;
        if (ix >= nvalid) ix = nvalid - 1;   // clamp: duplicate rows, discarded
        rows_s[tid] = d_perm[p + ix];
    }
    __syncthreads();

    const char* myrow = (const char*)(X + (size_t)rows_s[tid & 63] * HID);
    const char* wbase = (const char*)(d_wms + (size_t)g * (128 * WSTG_W));
    float* red = (float*)sm;
    gemm_core(sm, myrow, wbase, tid, red, mbs);

    float* pb = (float*)(sm + 4608);   // [64][17]
    if (tid < BM) {
        const bool valid = (tid < nvalid);
        float lg[NE];
#pragma unroll
        for (int e2 = 0; e2 < NE; e2++) lg[e2] = red[tid * 17 + e2];
        float mx = lg[0];
#pragma unroll
        for (int e2 = 1; e2 < NE; e2++) mx = fmaxf(mx, lg[e2]);
        float ex[NE], ss = 0.f;
#pragma unroll
        for (int e2 = 0; e2 < NE; e2++) { ex[e2] = __expf(lg[e2] - mx); ss += ex[e2]; }
        const float inv = 1.0f / ss;
#pragma unroll
        for (int e2 = 0; e2 < NE; e2++) pb[tid * 17 + e2] = valid ? ex[e2] * inv : 0.f;

        if (valid) {
            // top-4 by logit; strict > keeps lowest index on ties (lax.top_k order)
            float cur[NE];
#pragma unroll
            for (int e2 = 0; e2 < NE; e2++) cur[e2] = lg[e2];
            int eidx[4];
            float ev[4], den = 0.f;
#pragma unroll
            for (int j = 0; j < 4; j++) {
                float best = -3.4e38f;
                int bi = 0;
#pragma unroll
                for (int e2 = 0; e2 < NE; e2++)
                    if (cur[e2] > best) { best = cur[e2]; bi = e2; }
                cur[bi] = -3.4e38f;
                eidx[j] = bi;
                ev[j] = ex[bi];
                den += ex[bi];
            }
            // group prob cancels in normalization: final = ex_j / sum(top4 ex)
            const float invd = 1.0f / den;
            const int n = rows_s[tid];
#pragma unroll
            for (int j = 0; j < 4; j++) {
                out[(size_t)n * 4 + j] = ev[j] * invd;
                out[(size_t)N_TOK * 4 + (size_t)n * 4 + j] = (float)(g * NE + eidx[j]);
            }
        }
    }
    __syncthreads();
    if (tid < NE) {
        float s = 0.f;
        for (int t = 0; t < BM; t++) s += pb[t * 17 + tid];
        atomicAdd(&d_msum[tid], s);
    }
}

// ============================================================
// Finalize: aux loss (separate launch — fused version regressed)
// ============================================================
__global__ void k_final(float* __restrict__ out, int out_size)
{
    if (threadIdx.x == 0) {
        float a = 0.f;
        for (int i = 0; i < NG; i++) { float x = d_gsum[i] / (float)N_TOK; a += x * x; }
        for (int i = 0; i < NE; i++) { float x = d_msum[i] / (float)N_TOK; a += x * x; }
        out[out_size - 1] = a;
    }
}

// ============================================================
extern "C" void kernel_launch(void* const* d_in, const int* in_sizes, int n_in,
                              void* d_out, int out_size)
{
    const float* X  = (const float*)d_in[0];  // hidden_states [N, H]
    const float* W1 = (const float*)d_in[1];  // group_gate_w  [16, H]
    const float* WM = (const float*)d_in[2];  // mini_gates    [16, H, 16]
    float* out = (float*)d_out;               // [probs N*4 | indices N*4 | aux]

    cudaFuncSetAttribute(k_gemm1, cudaFuncAttributeMaxDynamicSharedMemorySize, SMEM_DYN);
    cudaFuncSetAttribute(k_gemm2, cudaFuncAttributeMaxDynamicSharedMemorySize, SMEM_DYN);

    k_prep<<<2304, 256>>>(W1, WM);                     // launch 1
    k_gemm1<<<N_TOK / BM, NTHR, SMEM_DYN>>>(X);        // launch 2
    k_scatter<<<N_TOK / 256, 256>>>();                 // launch 3
    k_gemm2<<<MAXBLK, NTHR, SMEM_DYN>>>(X, out);       // launch 4 (ncu slot)
    k_final<<<1, 32>>>(out, out_size);                 // launch 5
}